// round 16
// baseline (speedup 1.0000x reference)
#include <cuda_runtime.h>
#include <math.h>
#include <stdint.h>

#define DD   768
#define MAXK 150
#define MAXN 1500
#define MAXB 256
#define MAXM 256
#define BETA_C 0.1f

// ---- scratch (static device globals; no allocation) ----
__device__ float g_S[(size_t)MAXK * DD * DD];    // tf32-rounded S = R - I
__device__ float g_B[(size_t)MAXK * MAXM * DD];  // tf32-rounded x = ood - c_near
__device__ float g_c2[MAXN];
__device__ float g_dotin[MAXB * MAXN];
__device__ float g_dotood[MAXM * MAXN];
__device__ int   g_cnt[MAXK];
__device__ int   g_clist[MAXK * MAXN];
__device__ int   g_scnt[MAXK];
__device__ int   g_slist[MAXK * MAXB];
__device__ int   g_ballin[MAXB];
__device__ float g_din[MAXB];
__device__ float g_dnear[MAXK * MAXM];
__device__ float g_x2[MAXK * MAXM];
__device__ float g_xy[MAXK * MAXM];
__device__ float g_y2[MAXK * MAXM];
__device__ float g_eucin2[MAXB];

// ======================= helpers ===========================================
__device__ __forceinline__ uint32_t smem_to_u32(const void* p) {
    uint32_t a;
    asm("{ .reg .u64 t; cvta.to.shared.u64 t, %1; cvt.u32.u64 %0, t; }" : "=r"(a) : "l"(p));
    return a;
}
__device__ __forceinline__ uint32_t tf32_of(float x) {
    uint32_t h;
    asm("cvt.rna.tf32.f32 %0, %1;" : "=r"(h) : "f"(x));
    return h;
}
__device__ __forceinline__ float tf32r(float x) {
    return __uint_as_float(tf32_of(x));
}
__device__ __forceinline__ void mma_tf32(float* d, const uint32_t* a, const uint32_t* b) {
    asm volatile(
        "mma.sync.aligned.m16n8k8.row.col.f32.tf32.tf32.f32 "
        "{%0,%1,%2,%3}, {%4,%5,%6,%7}, {%8,%9}, {%0,%1,%2,%3};"
        : "+f"(d[0]), "+f"(d[1]), "+f"(d[2]), "+f"(d[3])
        : "r"(a[0]), "r"(a[1]), "r"(a[2]), "r"(a[3]), "r"(b[0]), "r"(b[1]));
}
__device__ __forceinline__ void cp16(uint32_t dst, const void* src) {
    asm volatile("cp.async.cg.shared.global [%0], [%1], 16;" :: "r"(dst), "l"(src));
}
#define CP_COMMIT() asm volatile("cp.async.commit_group;" ::: "memory")
#define CP_WAIT1()  asm volatile("cp.async.wait_group 1;" ::: "memory")
#define CP_WAIT0()  asm volatile("cp.async.wait_group 0;" ::: "memory")

// ======================= setup kernels =====================================
__global__ void abl_clist_all(const int* __restrict__ blab,
                              const int* __restrict__ labels, int N, int K, int B) {
    int t = threadIdx.x;
    for (int i = t; i < K; i += 256) { g_cnt[i] = 0; g_scnt[i] = 0; }
    __syncthreads();
    for (int n = t; n < N; n += 256) {
        int kk = blab[n];
        int pos = atomicAdd(&g_cnt[kk], 1);
        g_clist[kk * MAXN + pos] = n;
    }
    for (int b = t; b < B; b += 256) {
        int kk = labels[b];
        int pos = atomicAdd(&g_scnt[kk], 1);
        g_slist[kk * MAXB + pos] = b;
        g_eucin2[b] = 0.f;
    }
}

__global__ void abl_c2zero(const float* __restrict__ cent, int Nc, int totf) {
    int bid = blockIdx.x;
    if (bid < Nc) {
        __shared__ float sr[128];
        float s = 0.f;
        for (int j = threadIdx.x; j < DD; j += 128) {
            float v = cent[(size_t)bid * DD + j];
            s += v * v;
        }
        sr[threadIdx.x] = s;
        __syncthreads();
        for (int k = 64; k > 0; k >>= 1) {
            if (threadIdx.x < k) sr[threadIdx.x] += sr[threadIdx.x + k];
            __syncthreads();
        }
        if (threadIdx.x == 0) g_c2[bid] = sr[0];
    } else {
        int base = (bid - Nc) * 512 + threadIdx.x;
#pragma unroll
        for (int r = 0; r < 4; r++) {
            int i = base + r * 128;
            if (i < totf) {
                int half = totf / 2;
                if (i < half) g_dotin[i] = 0.f;
                else g_dotood[i - half] = 0.f;
            }
        }
    }
}

// build tf32-rounded S = R - I from packed L/U/Dd
__global__ void abl_build_S(const float* __restrict__ L, const float* __restrict__ U,
                            const float* __restrict__ Ddm, int NTRI) {
    int k = blockIdx.y;
    int tidx = blockIdx.x;
    int ti = 0;
    while ((ti + 1) * (ti + 2) / 2 <= tidx) ti++;
    int tj = tidx - ti * (ti + 1) / 2;

    const float* Lk = L + (size_t)k * NTRI;
    const float* Uk = U + (size_t)k * NTRI;
    float* Sk = g_S + (size_t)k * DD * DD;

    __shared__ float su[32][33];
    int tx = threadIdx.x & 31, ty = threadIdx.x >> 5;
#pragma unroll
    for (int s = 0; s < 4; s++) {
        int ry = ty + 8 * s;
        int r = ti * 32 + ry, c = tj * 32 + tx;
        if (r > c) {
            size_t p = (size_t)r * (r - 1) / 2 + c;
            Sk[(size_t)r * DD + c] = tf32r(Lk[p]);
            su[ry][tx] = Uk[p];
        } else if (r == c) {
            Sk[(size_t)r * DD + c] = tf32r(Ddm[(size_t)k * DD + r] - 1.0f);
        }
    }
    __syncthreads();
#pragma unroll
    for (int s = 0; s < 4; s++) {
        int ry = ty + 8 * s;
        int ro = tj * 32 + ry, co = ti * 32 + tx;
        if (co > ro) Sk[(size_t)ro * DD + co] = tf32r(su[tx][ry]);
    }
}

// ---- combined dot kernel ----
__global__ __launch_bounds__(256) void abl_dot_comb(const float* __restrict__ pooled,
                                                    const float* __restrict__ ood,
                                                    const float* __restrict__ cent,
                                                    int B, int M, int N) {
    __shared__ float sA[16][65];
    __shared__ float sB[16][65];
    int n0 = blockIdx.x * 64;
    int rows0 = blockIdx.y * 64;
    int isood = (rows0 >= B);
    const float* src = isood ? ood : pooled;
    int rbase = isood ? (rows0 - B) : rows0;
    int rcount = isood ? M : B;
    float* C = isood ? g_dotood : g_dotin;

    int ks0 = blockIdx.z * (DD / 4);
    int t = threadIdx.x, tx = t & 15, ty = t >> 4;
    float acc[4][4];
#pragma unroll
    for (int r = 0; r < 4; r++)
#pragma unroll
        for (int c = 0; c < 4; c++) acc[r][c] = 0.f;

    for (int j0 = ks0; j0 < ks0 + DD / 4; j0 += 16) {
#pragma unroll
        for (int e = 0; e < 4; e++) {
            int mm = ty + 16 * e;
            int m = rbase + mm;
            sA[tx][mm] = (m < rcount) ? src[(size_t)m * DD + j0 + tx] : 0.f;
        }
#pragma unroll
        for (int e = 0; e < 4; e++) {
            int nn = ty + 16 * e;
            int n = n0 + nn;
            sB[tx][nn] = (n < N) ? cent[(size_t)n * DD + j0 + tx] : 0.f;
        }
        __syncthreads();
#pragma unroll
        for (int kk = 0; kk < 16; kk++) {
            float a[4], b[4];
#pragma unroll
            for (int r = 0; r < 4; r++) a[r] = sA[kk][ty * 4 + r];
#pragma unroll
            for (int c = 0; c < 4; c++) b[c] = sB[kk][tx * 4 + c];
#pragma unroll
            for (int r = 0; r < 4; r++)
#pragma unroll
                for (int c = 0; c < 4; c++) acc[r][c] += a[r] * b[c];
        }
        __syncthreads();
    }
#pragma unroll
    for (int r = 0; r < 4; r++) {
        int m = rbase + ty * 4 + r;
        if (m >= rcount) continue;
#pragma unroll
        for (int c = 0; c < 4; c++) {
            int n = n0 + tx * 4 + c;
            if (n < N) atomicAdd(&C[(size_t)m * N + n], acc[r][c]);
        }
    }
}

// fused: nearest class-k ball, dnear, x (tf32-rounded store, exact x2), zero xy/y2
__global__ __launch_bounds__(256) void abl_near_b(const float* __restrict__ ood,
                                                  const float* __restrict__ cent,
                                                  const float* __restrict__ delta,
                                                  int M, int N) {
    int k = blockIdx.x;
    int mb = blockIdx.y * 64;
    __shared__ int snb[64];
    int t = threadIdx.x;
    if (t < 64) {
        int m = mb + t;
        int mc = (m < M) ? m : (M - 1);
        int cnt = g_cnt[k];
        float best = 3.4e38f;
        int bi = 0;
        for (int i = 0; i < cnt; i++) {
            int n = g_clist[k * MAXN + i];
            float s = g_c2[n] - 2.f * g_dotood[(size_t)mc * N + n];
            if (s < best) { best = s; bi = n; }
        }
        snb[t] = bi;
        if (m < M) {
            g_dnear[k * M + m] = delta[bi];
            g_xy[k * M + m] = 0.f;
            g_y2[k * M + m] = 0.f;
        }
    }
    __syncthreads();
    int row = t >> 2, quad = t & 3;
    int m = mb + row;
    int mc = (m < M) ? m : (M - 1);
    int nb = snb[row];
    float* bo = g_B + ((size_t)k * MAXM + mb + row) * DD;
    float sum2 = 0.f;
    for (int c4 = quad; c4 < DD / 4; c4 += 4) {
        float4 o = *(const float4*)(ood + (size_t)mc * DD + c4 * 4);
        float4 ce = *(const float4*)(cent + (size_t)nb * DD + c4 * 4);
        float4 v = make_float4(o.x - ce.x, o.y - ce.y, o.z - ce.z, o.w - ce.w);
        sum2 += v.x * v.x + v.y * v.y + v.z * v.z + v.w * v.w;   // exact
        v.x = tf32r(v.x); v.y = tf32r(v.y); v.z = tf32r(v.z); v.w = tf32r(v.w);
        *(float4*)(bo + c4 * 4) = v;
    }
    sum2 += __shfl_down_sync(0xffffffffu, sum2, 2, 4);
    sum2 += __shfl_down_sync(0xffffffffu, sum2, 1, 4);
    if (quad == 0 && m < M) g_x2[k * M + m] = sum2;
}

// ====== tf32 GEMM y = S_k . x^T : KC=16, 3-stage cp.async, 3 CTAs/SM =======
#define KC   16
#define NCH  (DD / KC)          // 48
#define LDSW 20                 // banks (20r+tig)%32 conflict-free
#define TILE_F (128 * LDSW)     // 2560
#define STAGE_F (2 * TILE_F)    // 5120
#define NSTAGE 3
#define SMEM_GEMM (NSTAGE * STAGE_F * 4)   // 61440 B
#define LDX  132

__global__ __launch_bounds__(256, 3) void abl_ood_s3(int M) {
    extern __shared__ float dsm[];
    uint32_t sb = smem_to_u32(dsm);
    __shared__ float scY[128];
    __shared__ float scX[128];

    int k = blockIdx.z;
    int rowBase = blockIdx.y * 128;
    int colBase = blockIdx.x * 128;

    const float* A = g_S + (size_t)k * DD * DD;
    const float* Bp = g_B + ((size_t)k * MAXM + colBase) * DD;

    int t = threadIdx.x, wid = t >> 5, lane = t & 31;
    int wm = (wid >> 2) * 64;
    int wn = (wid & 3) * 32;
    int gid = lane >> 2, tig = lane & 3;

    if (t < 128) { scY[t] = 0.f; scX[t] = 0.f; }

    float acc[4][4][4];
#pragma unroll
    for (int mt = 0; mt < 4; mt++)
#pragma unroll
        for (int nt = 0; nt < 4; nt++)
#pragma unroll
            for (int r = 0; r < 4; r++) acc[mt][nt][r] = 0.f;

    // one chunk = 128 rows x 16 floats per tile = 512 x 16B segs per tile
    auto load_chunk = [&](int c, int s) {
        int j0 = c * KC;
        uint32_t base = sb + (uint32_t)(s * STAGE_F) * 4u;
#pragma unroll
        for (int e = 0; e < 2; e++) {
            int idx = t + 256 * e;
            int row = idx >> 2, c4 = idx & 3;
            uint32_t soff = (uint32_t)(row * LDSW + c4 * 4) * 4u;
            cp16(base + soff, A + (size_t)(rowBase + row) * DD + j0 + c4 * 4);
            cp16(base + (uint32_t)TILE_F * 4u + soff, Bp + (size_t)row * DD + j0 + c4 * 4);
        }
    };

    load_chunk(0, 0);
    CP_COMMIT();
    load_chunk(1, 1);
    CP_COMMIT();

    for (int c = 0; c < NCH; c++) {
        if (c + 1 < NCH) CP_WAIT1(); else CP_WAIT0();
        __syncthreads();                  // chunk c ready; compute(c-1) done everywhere
        if (c + 2 < NCH) {
            load_chunk(c + 2, (c + 2) % NSTAGE);
            CP_COMMIT();
        }
        const float* sA = dsm + (c % NSTAGE) * STAGE_F;
        const float* sB = sA + TILE_F;
#pragma unroll
        for (int kt = 0; kt < 2; kt++) {
            int kb = kt * 8;
            uint32_t ah[4][4], bh[4][2];
#pragma unroll
            for (int mt = 0; mt < 4; mt++) {
                int r0 = (wm + mt * 16 + gid) * LDSW + kb + tig;
                int r1 = r0 + 8 * LDSW;
                ah[mt][0] = __float_as_uint(sA[r0]);
                ah[mt][1] = __float_as_uint(sA[r1]);
                ah[mt][2] = __float_as_uint(sA[r0 + 4]);
                ah[mt][3] = __float_as_uint(sA[r1 + 4]);
            }
#pragma unroll
            for (int nt = 0; nt < 4; nt++) {
                int n0 = (wn + nt * 8 + gid) * LDSW + kb + tig;
                bh[nt][0] = __float_as_uint(sB[n0]);
                bh[nt][1] = __float_as_uint(sB[n0 + 4]);
            }
#pragma unroll
            for (int mt = 0; mt < 4; mt++)
#pragma unroll
                for (int nt = 0; nt < 4; nt++)
                    mma_tf32(acc[mt][nt], ah[mt], bh[nt]);
        }
    }

    // ---- y^2 ----
#pragma unroll
    for (int nt = 0; nt < 4; nt++) {
        float y0 = 0.f, y1 = 0.f;
#pragma unroll
        for (int mt = 0; mt < 4; mt++) {
            y0 += acc[mt][nt][0] * acc[mt][nt][0] + acc[mt][nt][2] * acc[mt][nt][2];
            y1 += acc[mt][nt][1] * acc[mt][nt][1] + acc[mt][nt][3] * acc[mt][nt][3];
        }
#pragma unroll
        for (int o = 16; o >= 4; o >>= 1) {
            y0 += __shfl_down_sync(0xffffffffu, y0, o);
            y1 += __shfl_down_sync(0xffffffffu, y1, o);
        }
        if (lane < 4) {
            atomicAdd(&scY[wn + nt * 8 + 2 * lane], y0);
            atomicAdd(&scY[wn + nt * 8 + 2 * lane + 1], y1);
        }
    }

    __syncthreads();

    // ---- x.y via staged x-slice (2 halves of 64 cols; 64*132*4 = 33.8KB fits) ----
#pragma unroll 1
    for (int h = 0; h < 2; h++) {
#pragma unroll
        for (int e = 0; e < 8; e++) {
            int idx = t + 256 * e;
            int cc = idx >> 5, rq = idx & 31;
            *(float4*)&dsm[cc * LDX + rq * 4] =
                *(const float4*)(Bp + (size_t)(h * 64 + cc) * DD + rowBase + rq * 4);
        }
        __syncthreads();
        if ((wn >> 6) == h) {
#pragma unroll
            for (int nt = 0; nt < 4; nt++) {
                int col0 = wn + nt * 8 + 2 * tig - h * 64;
                float x0 = 0.f, x1 = 0.f;
#pragma unroll
                for (int mt = 0; mt < 4; mt++) {
                    int r0 = wm + 16 * mt + gid;
                    x0 += acc[mt][nt][0] * dsm[col0 * LDX + r0] +
                          acc[mt][nt][2] * dsm[col0 * LDX + r0 + 8];
                    x1 += acc[mt][nt][1] * dsm[(col0 + 1) * LDX + r0] +
                          acc[mt][nt][3] * dsm[(col0 + 1) * LDX + r0 + 8];
                }
#pragma unroll
                for (int o = 16; o >= 4; o >>= 1) {
                    x0 += __shfl_down_sync(0xffffffffu, x0, o);
                    x1 += __shfl_down_sync(0xffffffffu, x1, o);
                }
                if (lane < 4) {
                    atomicAdd(&scX[wn + nt * 8 + 2 * lane], x0);
                    atomicAdd(&scX[wn + nt * 8 + 2 * lane + 1], x1);
                }
            }
        }
        __syncthreads();
    }

    if (t < 128) {
        int col = colBase + t;
        if (col < M) {
            atomicAdd(&g_y2[k * M + col], scY[t]);
            atomicAdd(&g_xy[k * M + col], scX[t]);
        }
    }
}

// ======================= remaining kernels =================================
__global__ void abl_assign_in(const int* __restrict__ labels,
                              const float* __restrict__ delta, int B, int N) {
    int b = blockIdx.x * blockDim.x + threadIdx.x;
    if (b >= B) return;
    int lab = labels[b];
    int cnt = g_cnt[lab];
    float best = 3.4e38f;
    int bi = 0;
    for (int i = 0; i < cnt; i++) {
        int n = g_clist[lab * MAXN + i];
        float s = g_c2[n] - 2.f * g_dotin[(size_t)b * N + n];
        if (s < best) { best = s; bi = n; }
    }
    g_ballin[b] = bi;
    g_din[b] = delta[bi];
}

__global__ __launch_bounds__(256) void abl_indist2(const float* __restrict__ pooled,
                                                   const float* __restrict__ cent,
                                                   int B) {
    int k = blockIdx.x;
    int rc = blockIdx.y;
    int ns = g_scnt[k];
    if (ns == 0) return;

    __shared__ float sx[4][DD];
    __shared__ int sid[4];
    const float* Sk = g_S + (size_t)k * DD * DD;
    int t = threadIdx.x, w = t >> 5, lane = t & 31;

    for (int g0 = 0; g0 < ns; g0 += 4) {
        int gcnt = min(4, ns - g0);
        if (t < 4) sid[t] = (t < gcnt) ? g_slist[k * MAXB + g0 + t] : -1;
        __syncthreads();
        for (int gi = 0; gi < gcnt; gi++) {
            int s = sid[gi];
            int bid = g_ballin[s];
            for (int j = t; j < DD; j += 256)
                sx[gi][j] = pooled[(size_t)s * DD + j] - cent[(size_t)bid * DD + j];
        }
        __syncthreads();

        float wz[4] = {0.f, 0.f, 0.f, 0.f};
        for (int ii = 0; ii < 16; ii++) {
            int i = rc * 128 + w * 16 + ii;
            const float* row = Sk + (size_t)i * DD;
            float d0 = 0.f, d1 = 0.f, d2 = 0.f, d3 = 0.f;
            for (int j = lane * 4; j < DD; j += 128) {
                float4 sv = *(const float4*)(row + j);
                float4 x0 = *(const float4*)(&sx[0][j]);
                d0 += sv.x * x0.x + sv.y * x0.y + sv.z * x0.z + sv.w * x0.w;
                if (gcnt > 1) {
                    float4 x1 = *(const float4*)(&sx[1][j]);
                    d1 += sv.x * x1.x + sv.y * x1.y + sv.z * x1.z + sv.w * x1.w;
                }
                if (gcnt > 2) {
                    float4 x2 = *(const float4*)(&sx[2][j]);
                    d2 += sv.x * x2.x + sv.y * x2.y + sv.z * x2.z + sv.w * x2.w;
                }
                if (gcnt > 3) {
                    float4 x3 = *(const float4*)(&sx[3][j]);
                    d3 += sv.x * x3.x + sv.y * x3.y + sv.z * x3.z + sv.w * x3.w;
                }
            }
#pragma unroll
            for (int o = 16; o; o >>= 1) {
                d0 += __shfl_down_sync(0xffffffffu, d0, o);
                d1 += __shfl_down_sync(0xffffffffu, d1, o);
                d2 += __shfl_down_sync(0xffffffffu, d2, o);
                d3 += __shfl_down_sync(0xffffffffu, d3, o);
            }
            if (lane == 0) {
                float dd[4] = {d0, d1, d2, d3};
                for (int gi = 0; gi < gcnt; gi++) {
                    float z = sx[gi][i] + dd[gi];
                    wz[gi] += z * z;
                }
            }
        }
        if (lane == 0)
            for (int gi = 0; gi < gcnt; gi++)
                atomicAdd(&g_eucin2[sid[gi]], wz[gi]);
        __syncthreads();
    }
}

__global__ void abl_finalize(float* __restrict__ out, int B, int M, int K, int out_size) {
    __shared__ float sred[256];
    int t = threadIdx.x;

    float pl = 0.f, pn = 0.f, nn = 0.f;
    for (int b = t; b < B; b += 256) {
        float e = sqrtf(g_eucin2[b]);
        float d = g_din[b];
        pl += (d > e) ? expf(e - d) : (e - d);
        if (e > d) pn += 1.f;
        if (e < d) nn += 1.f;
    }
    float ns = 0.f;
    for (int m = t; m < M; m += 256) {
        float s = 0.f;
        for (int k = 0; k < K; k++) {
            float e2 = g_x2[k * M + m] + 2.f * g_xy[k * M + m] + g_y2[k * M + m];
            float e = sqrtf(fmaxf(e2, 0.f));
            float d = g_dnear[k * M + m];
            s += (d > e) ? (d - e + BETA_C) : BETA_C * expf(d - e);
        }
        ns += s;
    }

    float vals[4] = {pl, pn, nn, ns};
    float red[4];
    for (int v = 0; v < 4; v++) {
        sred[t] = vals[v];
        __syncthreads();
        for (int s2 = 128; s2 > 0; s2 >>= 1) {
            if (t < s2) sred[t] += sred[t + s2];
            __syncthreads();
        }
        red[v] = sred[0];
        __syncthreads();
    }
    if (t == 0) {
        float pos_mean = red[0] / (float)B;
        float neg_mean = red[3] / (float)M;
        if (out_size > 0) out[0] = pos_mean;
        if (out_size > 1) out[1] = neg_mean;
        if (out_size > 2) out[2] = red[1];
        if (out_size > 3) out[3] = red[2];
        if (out_size > 4) out[4] = pos_mean + neg_mean;
    }
}

// ---------------------------------------------------------------------------
extern "C" void kernel_launch(void* const* d_in, const int* in_sizes, int n_in,
                              void* d_out, int out_size) {
    const float* pooled = (const float*)d_in[0];
    const float* ood    = (const float*)d_in[1];
    const float* cent   = (const float*)d_in[2];
    const float* delta  = (const float*)d_in[3];
    const float* L      = (const float*)d_in[4];
    const float* U      = (const float*)d_in[5];
    const float* Ddm    = (const float*)d_in[6];
    const int*   labels = (const int*)d_in[7];
    const int*   blab   = (const int*)d_in[8];

    int B = in_sizes[0] / DD;
    int M = in_sizes[1] / DD;
    int N = in_sizes[3];
    int K = in_sizes[6] / DD;
    int NTRI = in_sizes[4] / K;

    if (B > MAXB) B = MAXB;
    if (M > MAXM) M = MAXM;
    if (N > MAXN) N = MAXN;
    if (K > MAXK) K = MAXK;

    int ntiles = (DD / 32) * (DD / 32 + 1) / 2;   // 300
    int totf = (B + M) * N;
    int zblocks = (totf + 511) / 512;

    static cudaStream_t s1 = nullptr, s2 = nullptr;
    static cudaEvent_t evFork = nullptr, evS = nullptr, evA = nullptr, evI = nullptr;
    static bool inited = false;
    if (!inited) {
        cudaStreamCreateWithFlags(&s1, cudaStreamNonBlocking);
        cudaStreamCreateWithFlags(&s2, cudaStreamNonBlocking);
        cudaEventCreateWithFlags(&evFork, cudaEventDisableTiming);
        cudaEventCreateWithFlags(&evS, cudaEventDisableTiming);
        cudaEventCreateWithFlags(&evA, cudaEventDisableTiming);
        cudaEventCreateWithFlags(&evI, cudaEventDisableTiming);
        cudaFuncSetAttribute(abl_ood_s3, cudaFuncAttributeMaxDynamicSharedMemorySize,
                             SMEM_GEMM);
        inited = true;
    }

    // --- main stream: setup chain ---
    abl_clist_all<<<1, 256>>>(blab, labels, N, K, B);
    abl_c2zero<<<N + zblocks, 128>>>(cent, N, totf);

    // --- fork: build_S concurrent with dot/near chain ---
    cudaEventRecord(evFork, 0);
    cudaStreamWaitEvent(s1, evFork, 0);
    abl_build_S<<<dim3(ntiles, K), 256, 0, s1>>>(L, U, Ddm, NTRI);
    cudaEventRecord(evS, s1);

    // --- main stream: dot products -> nearest/B -> assign ---
    abl_dot_comb<<<dim3((N + 63) / 64, (B + M) / 64, 4), 256>>>(pooled, ood, cent, B, M, N);
    abl_near_b<<<dim3(K, (M + 63) / 64), 256>>>(ood, cent, delta, M, N);
    abl_assign_in<<<(B + 255) / 256, 256>>>(labels, delta, B, N);
    cudaEventRecord(evA, 0);

    // --- GEMM on main stream (needs g_S + g_B) ---
    cudaStreamWaitEvent(0, evS, 0);
    abl_ood_s3<<<dim3((M + 127) / 128, DD / 128, K), 256, SMEM_GEMM>>>(M);

    // --- indist2 on s2, concurrent with GEMM (smem now allows co-residency) ---
    cudaStreamWaitEvent(s2, evS, 0);
    cudaStreamWaitEvent(s2, evA, 0);
    abl_indist2<<<dim3(K, DD / 128), 256, 0, s2>>>(pooled, cent, B);
    cudaEventRecord(evI, s2);

    // --- join and finalize ---
    cudaStreamWaitEvent(0, evI, 0);
    abl_finalize<<<1, 256>>>((float*)d_out, B, M, K, out_size);
}

// round 17
// speedup vs baseline: 1.2290x; 1.2290x over previous
#include <cuda_runtime.h>
#include <math.h>
#include <stdint.h>

#define DD   768
#define MAXK 150
#define MAXN 1500
#define MAXB 256
#define MAXM 256
#define BETA_C 0.1f

// ---- scratch (static device globals; no allocation) ----
__device__ float g_S[(size_t)MAXK * DD * DD];    // tf32-rounded S = R - I
__device__ float g_B[(size_t)MAXK * MAXM * DD];  // tf32-rounded x = ood - c_near
__device__ float g_c2[MAXN];
__device__ float g_dotood[MAXM * MAXN];
__device__ int   g_cnt[MAXK];
__device__ int   g_clist[MAXK * MAXN];
__device__ int   g_scnt[MAXK];
__device__ int   g_slist[MAXK * MAXB];
__device__ int   g_ballin[MAXB];
__device__ float g_din[MAXB];
__device__ float g_dnear[MAXK * MAXM];
__device__ float g_x2[MAXK * MAXM];
__device__ float g_xy[MAXK * MAXM];
__device__ float g_y2[MAXK * MAXM];
__device__ float g_eucin2[MAXB];

// ======================= helpers ===========================================
__device__ __forceinline__ uint32_t smem_to_u32(const void* p) {
    uint32_t a;
    asm("{ .reg .u64 t; cvta.to.shared.u64 t, %1; cvt.u32.u64 %0, t; }" : "=r"(a) : "l"(p));
    return a;
}
__device__ __forceinline__ uint32_t tf32_of(float x) {
    uint32_t h;
    asm("cvt.rna.tf32.f32 %0, %1;" : "=r"(h) : "f"(x));
    return h;
}
__device__ __forceinline__ float tf32r(float x) {
    return __uint_as_float(tf32_of(x));
}
__device__ __forceinline__ void mma_tf32(float* d, const uint32_t* a, const uint32_t* b) {
    asm volatile(
        "mma.sync.aligned.m16n8k8.row.col.f32.tf32.tf32.f32 "
        "{%0,%1,%2,%3}, {%4,%5,%6,%7}, {%8,%9}, {%0,%1,%2,%3};"
        : "+f"(d[0]), "+f"(d[1]), "+f"(d[2]), "+f"(d[3])
        : "r"(a[0]), "r"(a[1]), "r"(a[2]), "r"(a[3]), "r"(b[0]), "r"(b[1]));
}
__device__ __forceinline__ void cp16(uint32_t dst, const void* src) {
    asm volatile("cp.async.cg.shared.global [%0], [%1], 16;" :: "r"(dst), "l"(src));
}
#define CP_COMMIT() asm volatile("cp.async.commit_group;" ::: "memory")
#define CP_WAIT1()  asm volatile("cp.async.wait_group 1;" ::: "memory")
#define CP_WAIT0()  asm volatile("cp.async.wait_group 0;" ::: "memory")

// ======================= setup kernels =====================================
__global__ void abl_clist_all(const int* __restrict__ blab,
                              const int* __restrict__ labels, int N, int K, int B) {
    int t = threadIdx.x;
    for (int i = t; i < K; i += 256) { g_cnt[i] = 0; g_scnt[i] = 0; }
    __syncthreads();
    for (int n = t; n < N; n += 256) {
        int kk = blab[n];
        int pos = atomicAdd(&g_cnt[kk], 1);
        g_clist[kk * MAXN + pos] = n;
    }
    for (int b = t; b < B; b += 256) {
        int kk = labels[b];
        int pos = atomicAdd(&g_scnt[kk], 1);
        g_slist[kk * MAXB + pos] = b;
        g_eucin2[b] = 0.f;
    }
}

// blocks [0,Nc): centroid sumsq; blocks >=Nc: zero g_dotood
__global__ void abl_c2zero(const float* __restrict__ cent, int Nc, int totf) {
    int bid = blockIdx.x;
    if (bid < Nc) {
        __shared__ float sr[128];
        float s = 0.f;
        for (int j = threadIdx.x; j < DD; j += 128) {
            float v = cent[(size_t)bid * DD + j];
            s += v * v;
        }
        sr[threadIdx.x] = s;
        __syncthreads();
        for (int k = 64; k > 0; k >>= 1) {
            if (threadIdx.x < k) sr[threadIdx.x] += sr[threadIdx.x + k];
            __syncthreads();
        }
        if (threadIdx.x == 0) g_c2[bid] = sr[0];
    } else {
        int base = (bid - Nc) * 512 + threadIdx.x;
#pragma unroll
        for (int r = 0; r < 4; r++) {
            int i = base + r * 128;
            if (i < totf) g_dotood[i] = 0.f;
        }
    }
}

// build tf32-rounded S = R - I from packed L/U/Dd
__global__ void abl_build_S(const float* __restrict__ L, const float* __restrict__ U,
                            const float* __restrict__ Ddm, int NTRI) {
    int k = blockIdx.y;
    int tidx = blockIdx.x;
    int ti = 0;
    while ((ti + 1) * (ti + 2) / 2 <= tidx) ti++;
    int tj = tidx - ti * (ti + 1) / 2;

    const float* Lk = L + (size_t)k * NTRI;
    const float* Uk = U + (size_t)k * NTRI;
    float* Sk = g_S + (size_t)k * DD * DD;

    __shared__ float su[32][33];
    int tx = threadIdx.x & 31, ty = threadIdx.x >> 5;
#pragma unroll
    for (int s = 0; s < 4; s++) {
        int ry = ty + 8 * s;
        int r = ti * 32 + ry, c = tj * 32 + tx;
        if (r > c) {
            size_t p = (size_t)r * (r - 1) / 2 + c;
            Sk[(size_t)r * DD + c] = tf32r(Lk[p]);
            su[ry][tx] = Uk[p];
        } else if (r == c) {
            Sk[(size_t)r * DD + c] = tf32r(Ddm[(size_t)k * DD + r] - 1.0f);
        }
    }
    __syncthreads();
#pragma unroll
    for (int s = 0; s < 4; s++) {
        int ry = ty + 8 * s;
        int ro = tj * 32 + ry, co = ti * 32 + tx;
        if (co > ro) Sk[(size_t)ro * DD + co] = tf32r(su[tx][ry]);
    }
}

// ---- ood dot kernel: ood . cent^T with k-split 4, atomic accumulate ----
__global__ __launch_bounds__(256) void abl_dot_ood(const float* __restrict__ ood,
                                                   const float* __restrict__ cent,
                                                   int M, int N) {
    __shared__ float sA[16][65];
    __shared__ float sB[16][65];
    int n0 = blockIdx.x * 64;
    int rbase = blockIdx.y * 64;
    int ks0 = blockIdx.z * (DD / 4);
    int t = threadIdx.x, tx = t & 15, ty = t >> 4;
    float acc[4][4];
#pragma unroll
    for (int r = 0; r < 4; r++)
#pragma unroll
        for (int c = 0; c < 4; c++) acc[r][c] = 0.f;

    for (int j0 = ks0; j0 < ks0 + DD / 4; j0 += 16) {
#pragma unroll
        for (int e = 0; e < 4; e++) {
            int mm = ty + 16 * e;
            int m = rbase + mm;
            sA[tx][mm] = (m < M) ? ood[(size_t)m * DD + j0 + tx] : 0.f;
        }
#pragma unroll
        for (int e = 0; e < 4; e++) {
            int nn = ty + 16 * e;
            int n = n0 + nn;
            sB[tx][nn] = (n < N) ? cent[(size_t)n * DD + j0 + tx] : 0.f;
        }
        __syncthreads();
#pragma unroll
        for (int kk = 0; kk < 16; kk++) {
            float a[4], b[4];
#pragma unroll
            for (int r = 0; r < 4; r++) a[r] = sA[kk][ty * 4 + r];
#pragma unroll
            for (int c = 0; c < 4; c++) b[c] = sB[kk][tx * 4 + c];
#pragma unroll
            for (int r = 0; r < 4; r++)
#pragma unroll
                for (int c = 0; c < 4; c++) acc[r][c] += a[r] * b[c];
        }
        __syncthreads();
    }
#pragma unroll
    for (int r = 0; r < 4; r++) {
        int m = rbase + ty * 4 + r;
        if (m >= M) continue;
#pragma unroll
        for (int c = 0; c < 4; c++) {
            int n = n0 + tx * 4 + c;
            if (n < N) atomicAdd(&g_dotood[(size_t)m * N + n], acc[r][c]);
        }
    }
}

// fused: nearest class-k ball, dnear, x (tf32-rounded store, exact x2), zero xy/y2
__global__ __launch_bounds__(256) void abl_near_b(const float* __restrict__ ood,
                                                  const float* __restrict__ cent,
                                                  const float* __restrict__ delta,
                                                  int M, int N) {
    int k = blockIdx.x;
    int mb = blockIdx.y * 64;
    __shared__ int snb[64];
    int t = threadIdx.x;
    if (t < 64) {
        int m = mb + t;
        int mc = (m < M) ? m : (M - 1);
        int cnt = g_cnt[k];
        float best = 3.4e38f;
        int bi = 0;
        for (int i = 0; i < cnt; i++) {
            int n = g_clist[k * MAXN + i];
            float s = g_c2[n] - 2.f * g_dotood[(size_t)mc * N + n];
            if (s < best) { best = s; bi = n; }
        }
        snb[t] = bi;
        if (m < M) {
            g_dnear[k * M + m] = delta[bi];
            g_xy[k * M + m] = 0.f;
            g_y2[k * M + m] = 0.f;
        }
    }
    __syncthreads();
    int row = t >> 2, quad = t & 3;
    int m = mb + row;
    int mc = (m < M) ? m : (M - 1);
    int nb = snb[row];
    float* bo = g_B + ((size_t)k * MAXM + mb + row) * DD;
    float sum2 = 0.f;
    for (int c4 = quad; c4 < DD / 4; c4 += 4) {
        float4 o = *(const float4*)(ood + (size_t)mc * DD + c4 * 4);
        float4 ce = *(const float4*)(cent + (size_t)nb * DD + c4 * 4);
        float4 v = make_float4(o.x - ce.x, o.y - ce.y, o.z - ce.z, o.w - ce.w);
        sum2 += v.x * v.x + v.y * v.y + v.z * v.z + v.w * v.w;   // exact
        v.x = tf32r(v.x); v.y = tf32r(v.y); v.z = tf32r(v.z); v.w = tf32r(v.w);
        *(float4*)(bo + c4 * 4) = v;
    }
    sum2 += __shfl_down_sync(0xffffffffu, sum2, 2, 4);
    sum2 += __shfl_down_sync(0xffffffffu, sum2, 1, 4);
    if (quad == 0 && m < M) g_x2[k * M + m] = sum2;
}

// ============ tf32 GEMM y = S_k . x^T : KC=32, 3-stage cp.async ============
#define KC   32
#define NCH  (DD / KC)
#define LDSW 36
#define TILE_F (128 * LDSW)
#define STAGE_F (2 * TILE_F)
#define NSTAGE 3
#define SMEM_GEMM (NSTAGE * STAGE_F * 4)   // 110592 B
#define LDX  132

__global__ __launch_bounds__(256, 2) void abl_ood_s3(int M) {
    extern __shared__ float dsm[];
    uint32_t sb = smem_to_u32(dsm);
    __shared__ float scY[128];
    __shared__ float scX[128];

    int k = blockIdx.z;
    int rowBase = blockIdx.y * 128;
    int colBase = blockIdx.x * 128;

    const float* A = g_S + (size_t)k * DD * DD;
    const float* Bp = g_B + ((size_t)k * MAXM + colBase) * DD;

    int t = threadIdx.x, wid = t >> 5, lane = t & 31;
    int wm = (wid >> 2) * 64;
    int wn = (wid & 3) * 32;
    int gid = lane >> 2, tig = lane & 3;

    if (t < 128) { scY[t] = 0.f; scX[t] = 0.f; }

    float acc[4][4][4];
#pragma unroll
    for (int mt = 0; mt < 4; mt++)
#pragma unroll
        for (int nt = 0; nt < 4; nt++)
#pragma unroll
            for (int r = 0; r < 4; r++) acc[mt][nt][r] = 0.f;

    auto load_chunk = [&](int c, int s) {
        int j0 = c * KC;
        uint32_t base = sb + (uint32_t)(s * STAGE_F) * 4u;
#pragma unroll
        for (int e = 0; e < 4; e++) {
            int idx = t + 256 * e;
            int row = idx >> 3, c4 = idx & 7;
            uint32_t soff = (uint32_t)(row * LDSW + c4 * 4) * 4u;
            cp16(base + soff, A + (size_t)(rowBase + row) * DD + j0 + c4 * 4);
            cp16(base + (uint32_t)TILE_F * 4u + soff, Bp + (size_t)row * DD + j0 + c4 * 4);
        }
    };

    load_chunk(0, 0);
    CP_COMMIT();
    load_chunk(1, 1);
    CP_COMMIT();

    for (int c = 0; c < NCH; c++) {
        if (c + 1 < NCH) CP_WAIT1(); else CP_WAIT0();
        __syncthreads();
        if (c + 2 < NCH) {
            load_chunk(c + 2, (c + 2) % NSTAGE);
            CP_COMMIT();
        }
        const float* sA = dsm + (c % NSTAGE) * STAGE_F;
        const float* sB = sA + TILE_F;
#pragma unroll
        for (int kt = 0; kt < 4; kt++) {
            int kb = kt * 8;
            uint32_t ah[4][4], bh[4][2];
#pragma unroll
            for (int mt = 0; mt < 4; mt++) {
                int r0 = (wm + mt * 16 + gid) * LDSW + kb + tig;
                int r1 = r0 + 8 * LDSW;
                ah[mt][0] = __float_as_uint(sA[r0]);
                ah[mt][1] = __float_as_uint(sA[r1]);
                ah[mt][2] = __float_as_uint(sA[r0 + 4]);
                ah[mt][3] = __float_as_uint(sA[r1 + 4]);
            }
#pragma unroll
            for (int nt = 0; nt < 4; nt++) {
                int n0 = (wn + nt * 8 + gid) * LDSW + kb + tig;
                bh[nt][0] = __float_as_uint(sB[n0]);
                bh[nt][1] = __float_as_uint(sB[n0 + 4]);
            }
#pragma unroll
            for (int mt = 0; mt < 4; mt++)
#pragma unroll
                for (int nt = 0; nt < 4; nt++)
                    mma_tf32(acc[mt][nt], ah[mt], bh[nt]);
        }
    }

    // ---- y^2 ----
#pragma unroll
    for (int nt = 0; nt < 4; nt++) {
        float y0 = 0.f, y1 = 0.f;
#pragma unroll
        for (int mt = 0; mt < 4; mt++) {
            y0 += acc[mt][nt][0] * acc[mt][nt][0] + acc[mt][nt][2] * acc[mt][nt][2];
            y1 += acc[mt][nt][1] * acc[mt][nt][1] + acc[mt][nt][3] * acc[mt][nt][3];
        }
#pragma unroll
        for (int o = 16; o >= 4; o >>= 1) {
            y0 += __shfl_down_sync(0xffffffffu, y0, o);
            y1 += __shfl_down_sync(0xffffffffu, y1, o);
        }
        if (lane < 4) {
            atomicAdd(&scY[wn + nt * 8 + 2 * lane], y0);
            atomicAdd(&scY[wn + nt * 8 + 2 * lane + 1], y1);
        }
    }

    __syncthreads();

    // ---- x.y via staged x-slice ----
#pragma unroll 1
    for (int h = 0; h < 2; h++) {
#pragma unroll
        for (int e = 0; e < 8; e++) {
            int idx = t + 256 * e;
            int cc = idx >> 5, rq = idx & 31;
            *(float4*)&dsm[cc * LDX + rq * 4] =
                *(const float4*)(Bp + (size_t)(h * 64 + cc) * DD + rowBase + rq * 4);
        }
        __syncthreads();
        if ((wn >> 6) == h) {
#pragma unroll
            for (int nt = 0; nt < 4; nt++) {
                int col0 = wn + nt * 8 + 2 * tig - h * 64;
                float x0 = 0.f, x1 = 0.f;
#pragma unroll
                for (int mt = 0; mt < 4; mt++) {
                    int r0 = wm + 16 * mt + gid;
                    x0 += acc[mt][nt][0] * dsm[col0 * LDX + r0] +
                          acc[mt][nt][2] * dsm[col0 * LDX + r0 + 8];
                    x1 += acc[mt][nt][1] * dsm[(col0 + 1) * LDX + r0] +
                          acc[mt][nt][3] * dsm[(col0 + 1) * LDX + r0 + 8];
                }
#pragma unroll
                for (int o = 16; o >= 4; o >>= 1) {
                    x0 += __shfl_down_sync(0xffffffffu, x0, o);
                    x1 += __shfl_down_sync(0xffffffffu, x1, o);
                }
                if (lane < 4) {
                    atomicAdd(&scX[wn + nt * 8 + 2 * lane], x0);
                    atomicAdd(&scX[wn + nt * 8 + 2 * lane + 1], x1);
                }
            }
        }
        __syncthreads();
    }

    if (t < 128) {
        int col = colBase + t;
        if (col < M) {
            atomicAdd(&g_y2[k * M + col], scY[t]);
            atomicAdd(&g_xy[k * M + col], scX[t]);
        }
    }
}

// ======================= remaining kernels =================================
// warp-per-sample nearest same-class ball via direct dots (~10 balls each)
__global__ void abl_assign_fused(const float* __restrict__ pooled,
                                 const float* __restrict__ cent,
                                 const float* __restrict__ delta,
                                 const int* __restrict__ labels, int B) {
    int w = threadIdx.x >> 5, lane = threadIdx.x & 31;
    int b = blockIdx.x * 8 + w;
    if (b >= B) return;
    int lab = labels[b];
    int cnt = g_cnt[lab];
    const float4* prow = (const float4*)(pooled + (size_t)b * DD);
    float4 pc[6];
#pragma unroll
    for (int j = 0; j < 6; j++) pc[j] = prow[lane + 32 * j];
    float best = 3.4e38f;
    int bi = 0;
    for (int i = 0; i < cnt; i++) {
        int n = g_clist[lab * MAXN + i];
        const float4* crow = (const float4*)(cent + (size_t)n * DD);
        float dot = 0.f;
#pragma unroll
        for (int j = 0; j < 6; j++) {
            float4 cv = crow[lane + 32 * j];
            dot += pc[j].x * cv.x + pc[j].y * cv.y + pc[j].z * cv.z + pc[j].w * cv.w;
        }
#pragma unroll
        for (int o = 16; o; o >>= 1) dot += __shfl_down_sync(0xffffffffu, dot, o);
        dot = __shfl_sync(0xffffffffu, dot, 0);
        float d2 = g_c2[n] - 2.f * dot;
        if (d2 < best) { best = d2; bi = n; }
    }
    if (lane == 0) {
        g_ballin[b] = bi;
        g_din[b] = delta[bi];
    }
}

__global__ __launch_bounds__(256) void abl_indist2(const float* __restrict__ pooled,
                                                   const float* __restrict__ cent,
                                                   int B) {
    int k = blockIdx.x;
    int rc = blockIdx.y;
    int ns = g_scnt[k];
    if (ns == 0) return;

    __shared__ float sx[4][DD];
    __shared__ int sid[4];
    const float* Sk = g_S + (size_t)k * DD * DD;
    int t = threadIdx.x, w = t >> 5, lane = t & 31;

    for (int g0 = 0; g0 < ns; g0 += 4) {
        int gcnt = min(4, ns - g0);
        if (t < 4) sid[t] = (t < gcnt) ? g_slist[k * MAXB + g0 + t] : -1;
        __syncthreads();
        for (int gi = 0; gi < gcnt; gi++) {
            int s = sid[gi];
            int bid = g_ballin[s];
            for (int j = t; j < DD; j += 256)
                sx[gi][j] = pooled[(size_t)s * DD + j] - cent[(size_t)bid * DD + j];
        }
        __syncthreads();

        float wz[4] = {0.f, 0.f, 0.f, 0.f};
        for (int ii = 0; ii < 16; ii++) {
            int i = rc * 128 + w * 16 + ii;
            const float* row = Sk + (size_t)i * DD;
            float d0 = 0.f, d1 = 0.f, d2 = 0.f, d3 = 0.f;
            for (int j = lane * 4; j < DD; j += 128) {
                float4 sv = *(const float4*)(row + j);
                float4 x0 = *(const float4*)(&sx[0][j]);
                d0 += sv.x * x0.x + sv.y * x0.y + sv.z * x0.z + sv.w * x0.w;
                if (gcnt > 1) {
                    float4 x1 = *(const float4*)(&sx[1][j]);
                    d1 += sv.x * x1.x + sv.y * x1.y + sv.z * x1.z + sv.w * x1.w;
                }
                if (gcnt > 2) {
                    float4 x2 = *(const float4*)(&sx[2][j]);
                    d2 += sv.x * x2.x + sv.y * x2.y + sv.z * x2.z + sv.w * x2.w;
                }
                if (gcnt > 3) {
                    float4 x3 = *(const float4*)(&sx[3][j]);
                    d3 += sv.x * x3.x + sv.y * x3.y + sv.z * x3.z + sv.w * x3.w;
                }
            }
#pragma unroll
            for (int o = 16; o; o >>= 1) {
                d0 += __shfl_down_sync(0xffffffffu, d0, o);
                d1 += __shfl_down_sync(0xffffffffu, d1, o);
                d2 += __shfl_down_sync(0xffffffffu, d2, o);
                d3 += __shfl_down_sync(0xffffffffu, d3, o);
            }
            if (lane == 0) {
                float dd[4] = {d0, d1, d2, d3};
                for (int gi = 0; gi < gcnt; gi++) {
                    float z = sx[gi][i] + dd[gi];
                    wz[gi] += z * z;
                }
            }
        }
        if (lane == 0)
            for (int gi = 0; gi < gcnt; gi++)
                atomicAdd(&g_eucin2[sid[gi]], wz[gi]);
        __syncthreads();
    }
}

__global__ void abl_finalize(float* __restrict__ out, int B, int M, int K, int out_size) {
    __shared__ float sred[256];
    int t = threadIdx.x;

    float pl = 0.f, pn = 0.f, nn = 0.f;
    for (int b = t; b < B; b += 256) {
        float e = sqrtf(g_eucin2[b]);
        float d = g_din[b];
        pl += (d > e) ? expf(e - d) : (e - d);
        if (e > d) pn += 1.f;
        if (e < d) nn += 1.f;
    }
    float ns = 0.f;
    for (int m = t; m < M; m += 256) {
        float s = 0.f;
        for (int k = 0; k < K; k++) {
            float e2 = g_x2[k * M + m] + 2.f * g_xy[k * M + m] + g_y2[k * M + m];
            float e = sqrtf(fmaxf(e2, 0.f));
            float d = g_dnear[k * M + m];
            s += (d > e) ? (d - e + BETA_C) : BETA_C * expf(d - e);
        }
        ns += s;
    }

    float vals[4] = {pl, pn, nn, ns};
    float red[4];
    for (int v = 0; v < 4; v++) {
        sred[t] = vals[v];
        __syncthreads();
        for (int s2 = 128; s2 > 0; s2 >>= 1) {
            if (t < s2) sred[t] += sred[t + s2];
            __syncthreads();
        }
        red[v] = sred[0];
        __syncthreads();
    }
    if (t == 0) {
        float pos_mean = red[0] / (float)B;
        float neg_mean = red[3] / (float)M;
        if (out_size > 0) out[0] = pos_mean;
        if (out_size > 1) out[1] = neg_mean;
        if (out_size > 2) out[2] = red[1];
        if (out_size > 3) out[3] = red[2];
        if (out_size > 4) out[4] = pos_mean + neg_mean;
    }
}

// ---------------------------------------------------------------------------
extern "C" void kernel_launch(void* const* d_in, const int* in_sizes, int n_in,
                              void* d_out, int out_size) {
    const float* pooled = (const float*)d_in[0];
    const float* ood    = (const float*)d_in[1];
    const float* cent   = (const float*)d_in[2];
    const float* delta  = (const float*)d_in[3];
    const float* L      = (const float*)d_in[4];
    const float* U      = (const float*)d_in[5];
    const float* Ddm    = (const float*)d_in[6];
    const int*   labels = (const int*)d_in[7];
    const int*   blab   = (const int*)d_in[8];

    int B = in_sizes[0] / DD;
    int M = in_sizes[1] / DD;
    int N = in_sizes[3];
    int K = in_sizes[6] / DD;
    int NTRI = in_sizes[4] / K;

    if (B > MAXB) B = MAXB;
    if (M > MAXM) M = MAXM;
    if (N > MAXN) N = MAXN;
    if (K > MAXK) K = MAXK;

    int ntiles = (DD / 32) * (DD / 32 + 1) / 2;   // 300
    int totf = M * N;
    int zblocks = (totf + 511) / 512;

    static cudaStream_t s1 = nullptr, s2 = nullptr;
    static cudaEvent_t evFork = nullptr, evS = nullptr, evA = nullptr, evI = nullptr;
    static bool inited = false;
    if (!inited) {
        cudaStreamCreateWithFlags(&s1, cudaStreamNonBlocking);
        cudaStreamCreateWithFlags(&s2, cudaStreamNonBlocking);
        cudaEventCreateWithFlags(&evFork, cudaEventDisableTiming);
        cudaEventCreateWithFlags(&evS, cudaEventDisableTiming);
        cudaEventCreateWithFlags(&evA, cudaEventDisableTiming);
        cudaEventCreateWithFlags(&evI, cudaEventDisableTiming);
        cudaFuncSetAttribute(abl_ood_s3, cudaFuncAttributeMaxDynamicSharedMemorySize,
                             SMEM_GEMM);
        inited = true;
    }

    // --- main stream: setup chain ---
    abl_clist_all<<<1, 256>>>(blab, labels, N, K, B);
    abl_c2zero<<<N + zblocks, 128>>>(cent, N, totf);

    // --- fork: build_S concurrent with dot/near chain ---
    cudaEventRecord(evFork, 0);
    cudaStreamWaitEvent(s1, evFork, 0);
    abl_build_S<<<dim3(ntiles, K), 256, 0, s1>>>(L, U, Ddm, NTRI);
    cudaEventRecord(evS, s1);

    // --- main stream: ood dots -> nearest/B -> in-branch assign ---
    abl_dot_ood<<<dim3((N + 63) / 64, (M + 63) / 64, 4), 256>>>(ood, cent, M, N);
    abl_near_b<<<dim3(K, (M + 63) / 64), 256>>>(ood, cent, delta, M, N);
    abl_assign_fused<<<(B + 7) / 8, 256>>>(pooled, cent, delta, labels, B);
    cudaEventRecord(evA, 0);

    // --- GEMM on main stream (needs g_S + g_B) ---
    cudaStreamWaitEvent(0, evS, 0);
    abl_ood_s3<<<dim3((M + 127) / 128, DD / 128, K), 256, SMEM_GEMM>>>(M);

    // --- indist2 on s2, fills GEMM tail ---
    cudaStreamWaitEvent(s2, evS, 0);
    cudaStreamWaitEvent(s2, evA, 0);
    abl_indist2<<<dim3(K, DD / 128), 256, 0, s2>>>(pooled, cent, B);
    cudaEventRecord(evI, s2);

    // --- join and finalize ---
    cudaStreamWaitEvent(0, evI, 0);
    abl_finalize<<<1, 256>>>((float*)d_out, B, M, K, out_size);
}